// round 13
// baseline (speedup 1.0000x reference)
#include <cuda_runtime.h>
#include <math.h>

// Problem constants
#define Vv 32000
#define Ee 512
#define Hh 512
#define G4 2048   // 4*H
#define Bb 64
#define Tt 256
#define GRID 128  // persistent CTAs, 1/SM -> all co-resident
#define NT 512    // threads per CTA (16 warps)

typedef unsigned long long ull;

// ---------------- device scratch ----------------
// Activations plain [k][b] layout: idx = k*64 + b.
__device__ float g_WT_fc[(size_t)Ee * Vv];   // [k][v] transposed W_fc
__device__ float g_h[2][2][Hh * Bb];         // [ping][layer][k*64+b]
__device__ float g_x[Ee * Bb];               // [k*64+b]
__device__ ull   g_amax[Bb];
__device__ unsigned g_bar_count;
__device__ volatile unsigned g_bar_gen;

// ---------------- packed f32x2 FMA helpers ----------------
__device__ __forceinline__ void ffma2(ull& d, ull a, ull b) {
    asm("fma.rn.f32x2 %0, %1, %2, %0;" : "+l"(d) : "l"(a), "l"(b));
}
__device__ __forceinline__ ull pack2(float v) {
    ull r; asm("mov.b64 %0, {%1, %1};" : "=l"(r) : "f"(v)); return r;
}
__device__ __forceinline__ float2 unpack2(ull a) {
    float2 r; asm("mov.b64 {%0, %1}, %2;" : "=f"(r.x), "=f"(r.y) : "l"(a)); return r;
}
__device__ __forceinline__ ull amax_pack(float f, int idx) {
    unsigned b = __float_as_uint(f);
    unsigned key = (b & 0x80000000u) ? ~b : (b | 0x80000000u);
    return ((ull)key << 32) | (ull)(0xFFFFFFFFu - (unsigned)idx);
}

// ---------------- grid-wide barrier ----------------
__device__ __forceinline__ void gsync() {
    __threadfence();
    __syncthreads();
    if (threadIdx.x == 0) {
        unsigned gen = g_bar_gen;
        unsigned t = atomicAdd(&g_bar_count, 1u);
        if (t == GRID - 1) {
            g_bar_count = 0;
            __threadfence();
            g_bar_gen = gen + 1;
        } else {
            while (g_bar_gen == gen) { }
        }
    }
    __syncthreads();
}

// smem map (floats): [0, 32768) gate weights; [32768, 40960) staging / scratch
#define STG_OFF 32768

// ---------------- LSTM layer ----------------
// thread: m = tid>>8 (0 = W_ih/inp, 1 = W_hh/hin), u = (tid>>6)&3, b = tid&63.
// Acts staged cooperatively in 32-k chunks (each element read ONCE per CTA).
__device__ __forceinline__ void lstm_layer(
    float* wsm, int layer,
    const float* __restrict__ inp, const float* __restrict__ hin,
    float* __restrict__ hout, float& creg,
    const float* __restrict__ bih, const float* __restrict__ bhh,
    int cta, int tid)
{
    float* stg = wsm + STG_OFF;              // 2 bufs x (2 matrices x 2048 floats)
    int m = tid >> 8, u = (tid >> 6) & 3, b = tid & 63;
    int i = tid & 255;
    const float* src = m ? hin : inp;
    const ulonglong2* wq =
        (const ulonglong2*)&wsm[(unsigned)(layer * 8 + m * 4 + u) * 2048];
    ull acc01 = 0ull, acc23 = 0ull;

    // stage chunk 0
    {
        float4 v0 = __ldcg((const float4*)src + i * 2);
        float4 v1 = __ldcg((const float4*)src + i * 2 + 1);
        *(float4*)&stg[m * 2048 + i * 8]     = v0;
        *(float4*)&stg[m * 2048 + i * 8 + 4] = v1;
    }
    __syncthreads();
    int d = 0;
    #pragma unroll 1
    for (int c = 0; c < 16; c++) {
        float4 n0, n1;
        if (c < 15) {
            const float4* np = (const float4*)(src + (c + 1) * 2048);
            n0 = __ldcg(np + i * 2);
            n1 = __ldcg(np + i * 2 + 1);
        }
        const float* ab = stg + d * 4096 + m * 2048 + b;
        const ulonglong2* wc = wq + c * 32;
        #pragma unroll
        for (int kk = 0; kk < 32; kk++) {
            ulonglong2 wv = wc[kk];
            ull ap = pack2(ab[kk * 64]);
            ffma2(acc01, wv.x, ap);
            ffma2(acc23, wv.y, ap);
        }
        if (c < 15) {
            float* dst = stg + (d ^ 1) * 4096 + m * 2048;
            *(float4*)&dst[i * 8]     = n0;
            *(float4*)&dst[i * 8 + 4] = n1;
        }
        __syncthreads();
        d ^= 1;
    }

    // combine halves: m=1 writes partials, m=0 finishes
    ull* cb = (ull*)(wsm + STG_OFF);
    if (m) { cb[i * 2] = acc01; cb[i * 2 + 1] = acc23; }
    __syncthreads();
    if (!m) {
        float2 a01 = unpack2(acc01), a23 = unpack2(acc23);
        float2 h01 = unpack2(cb[tid * 2]), h23 = unpack2(cb[tid * 2 + 1]);
        int j0 = cta * 4 + u;
        float iv = (a01.x + h01.x) + bih[j0]        + bhh[j0];
        float fv = (a01.y + h01.y) + bih[512 + j0]  + bhh[512 + j0];
        float gv = (a23.x + h23.x) + bih[1024 + j0] + bhh[1024 + j0];
        float ov = (a23.y + h23.y) + bih[1536 + j0] + bhh[1536 + j0];
        float ig = 1.0f / (1.0f + expf(-iv));
        float fg = 1.0f / (1.0f + expf(-fv));
        float og = 1.0f / (1.0f + expf(-ov));
        float cn = fg * creg + ig * tanhf(gv);
        float hn = og * tanhf(cn);
        creg = cn;
        __stcg(&hout[j0 * Bb + b], hn);
    }
    __syncthreads();
}

// ---------------- single persistent kernel ----------------
__global__ void __launch_bounds__(NT, 1)
kmain(const int* __restrict__ x, const float* __restrict__ emb,
      const float* __restrict__ W_ih, const float* __restrict__ W_hh,
      const float* __restrict__ b_ih, const float* __restrict__ b_hh,
      const float* __restrict__ W_fc, const float* __restrict__ bfc,
      float* __restrict__ out)
{
    extern __shared__ float wsm[];
    __shared__ int s_tok;

    int tid = threadIdx.x;
    int cta = blockIdx.x;

    // ================= per-replay init =================
    {   // zero h ping 0, both layers (65536 floats = 32768 float2)
        int gt = cta * NT + tid;
        if (gt < 32768) ((float2*)&g_h[0][0][0])[gt] = make_float2(0.0f, 0.0f);
    }
    if (cta < Bb && tid < 256) {             // x0 = embedding[x[:,0]]
        int tok = x[cta * Tt];
        float2 e2 = ((const float2*)(emb + (size_t)tok * Ee))[tid];
        g_x[(2 * tid) * Bb + cta]     = e2.x;
        g_x[(2 * tid + 1) * Bb + cta] = e2.y;
    }
    // gate weights -> smem: row r = layer*8 + m*4 + u; wsm[r][k] = (wi,wf,wg,wo)
    #pragma unroll 1
    for (int r = 0; r < 16; r++) {
        int l = r >> 3, m = (r >> 2) & 1, u = r & 3;
        const float* base = (m ? W_hh : W_ih) + (size_t)l * G4 * 512
                            + (size_t)(cta * 4 + u) * 512;
        int k = tid;                         // 0..511
        float4 wv;
        wv.x = base[k];
        wv.y = base[(size_t)512 * 512 + k];
        wv.z = base[(size_t)1024 * 512 + k];
        wv.w = base[(size_t)1536 * 512 + k];
        *(float4*)&wsm[r * 2048 + k * 4] = wv;
    }
    // transpose W_fc -> g_WT_fc [k][v]: 250 v per CTA, 2 threads per v (k halves)
    if (tid < 500) {
        int v = cta * 250 + (tid >> 1);
        int h0 = (tid & 1) * 64;
        const float4* src = (const float4*)(W_fc + (size_t)v * Ee);
        #pragma unroll 4
        for (int kq = h0; kq < h0 + 64; kq++) {
            float4 r = src[kq];
            size_t k = (size_t)kq * 4;
            g_WT_fc[k * Vv + v]       = r.x;
            g_WT_fc[(k + 1) * Vv + v] = r.y;
            g_WT_fc[(k + 2) * Vv + v] = r.z;
            g_WT_fc[(k + 3) * Vv + v] = r.w;
        }
    }
    if (cta == 0 && tid < Bb) g_amax[tid] = 0ull;

    float creg0 = 0.0f, creg1 = 0.0f;
    gsync();

    // ================= timestep loop =================
    for (int t = 0; t < Tt; t++) {
        int pi = t & 1, po = pi ^ 1;

        lstm_layer(wsm, 0, g_x, &g_h[pi][0][0], &g_h[po][0][0], creg0,
                   b_ih, b_hh, cta, tid);
        gsync();

        lstm_layer(wsm, 1, &g_h[po][0][0], &g_h[pi][1][0], &g_h[po][1][0], creg1,
                   b_ih + G4, b_hh + G4, cta, tid);
        gsync();

        // ---- FC head: warp owns 16 v (uniform weights), lane owns batch-pair ----
        if (cta < 125) {
            int w = tid >> 5, lane = tid & 31;
            int v0 = cta * 256 + w * 16;
            int b0 = lane * 2;
            const float* hsrc = &g_h[po][1][0];
            const float* Wb = g_WT_fc + v0;
            float* stg = wsm + STG_OFF;          // 2 bufs x 2048 floats

            ull acc[16];
            #pragma unroll
            for (int v = 0; v < 16; v++) acc[v] = 0ull;

            // stage chunk 0 (32 k x 64 b = 2048 floats)
            { float4 v4 = __ldcg((const float4*)hsrc + tid); *(float4*)&stg[tid * 4] = v4; }
            // weight pipeline: k=0, k=1
            float4 wA[4], wB[4];
            #pragma unroll
            for (int j = 0; j < 4; j++) wA[j] = __ldcs((const float4*)Wb + j);
            #pragma unroll
            for (int j = 0; j < 4; j++) wB[j] = __ldcs((const float4*)(Wb + Vv) + j);
            __syncthreads();

            int d = 0;
            #pragma unroll 1
            for (int c = 0; c < 16; c++) {
                float4 nst;
                if (c < 15) nst = __ldcg((const float4*)(hsrc + (c + 1) * 2048) + tid);
                const float* ab = stg + d * 2048 + b0;
                #pragma unroll
                for (int kk = 0; kk < 32; kk += 2) {
                    int kg = c * 32 + kk;
                    float4 nA[4], nB[4];
                    {
                        int k2 = (kg + 2 < 512) ? kg + 2 : 0;
                        int k3 = (kg + 3 < 512) ? kg + 3 : 0;
                        const float4* p2 = (const float4*)(Wb + (size_t)k2 * Vv);
                        const float4* p3 = (const float4*)(Wb + (size_t)k3 * Vv);
                        #pragma unroll
                        for (int j = 0; j < 4; j++) { nA[j] = __ldcs(p2 + j); nB[j] = __ldcs(p3 + j); }
                    }
                    ull a0 = *(const ull*)(ab + kk * 64);
                    ull a1 = *(const ull*)(ab + (kk + 1) * 64);
                    const float* wf0 = (const float*)wA;
                    const float* wf1 = (const float*)wB;
                    #pragma unroll
                    for (int v = 0; v < 16; v++) ffma2(acc[v], a0, pack2(wf0[v]));
                    #pragma unroll
                    for (int v = 0; v < 16; v++) ffma2(acc[v], a1, pack2(wf1[v]));
                    #pragma unroll
                    for (int j = 0; j < 4; j++) { wA[j] = nA[j]; wB[j] = nB[j]; }
                }
                if (c < 15) *(float4*)&stg[(d ^ 1) * 2048 + tid * 4] = nst;
                __syncthreads();
                d ^= 1;
            }

            // bias + epilogue
            float bias[16];
            {
                const float4* bp = (const float4*)(bfc + v0);
                #pragma unroll
                for (int j = 0; j < 4; j++) {
                    float4 bq = bp[j];
                    bias[j * 4] = bq.x; bias[j * 4 + 1] = bq.y;
                    bias[j * 4 + 2] = bq.z; bias[j * 4 + 3] = bq.w;
                }
            }
            if (t == Tt - 1) {
                #pragma unroll
                for (int v = 0; v < 16; v++) {
                    float2 t2 = unpack2(acc[v]);
                    out[(size_t)b0 * Vv + v0 + v]       = t2.x + bias[v];
                    out[(size_t)(b0 + 1) * Vv + v0 + v] = t2.y + bias[v];
                }
            } else {
                float mv0 = -1e30f, mv1 = -1e30f; int mi0 = 0, mi1 = 0;
                #pragma unroll
                for (int v = 0; v < 16; v++) {
                    float2 t2 = unpack2(acc[v]);
                    float e0 = t2.x + bias[v], e1 = t2.y + bias[v];
                    if (e0 > mv0) { mv0 = e0; mi0 = v0 + v; }
                    if (e1 > mv1) { mv1 = e1; mi1 = v0 + v; }
                }
                float* swv = wsm + STG_OFF;          // 16*64 floats
                int*   swi = (int*)(wsm + STG_OFF + 1024);
                __syncthreads();                     // staging now free
                swv[w * 64 + b0] = mv0;      swi[w * 64 + b0] = mi0;
                swv[w * 64 + b0 + 1] = mv1;  swi[w * 64 + b0 + 1] = mi1;
                __syncthreads();
                if (tid < 64) {
                    float mv = swv[tid]; int mi = swi[tid];
                    #pragma unroll
                    for (int ww = 1; ww < 16; ww++) {
                        float ovv = swv[ww * 64 + tid]; int oii = swi[ww * 64 + tid];
                        if (ovv > mv || (ovv == mv && oii < mi)) { mv = ovv; mi = oii; }
                    }
                    atomicMax(&g_amax[tid], amax_pack(mv, mi));
                }
            }
        }
        gsync();

        // ---- pick token, gather next embedding into g_x ----
        if (t < Tt - 1 && cta < Bb) {
            if (tid == 0) {
                ull pv = __ldcg((const ull*)&g_amax[cta]);
                s_tok = (int)(0xFFFFFFFFu - (unsigned)(pv & 0xFFFFFFFFull));
                atomicExch(&g_amax[cta], 0ull);
            }
            __syncthreads();
            if (tid < 256) {
                int tok = s_tok;
                float2 e2 = *(const float2*)(emb + (size_t)tok * Ee + tid * 2);
                __stcg(&g_x[(tid * 2) * Bb + cta],     e2.x);
                __stcg(&g_x[(tid * 2 + 1) * Bb + cta], e2.y);
            }
        }
        gsync();
    }
}

// ---------------- host driver ----------------
extern "C" void kernel_launch(void* const* d_in, const int* in_sizes, int n_in,
                              void* d_out, int out_size) {
    const int*   x    = (const int*)d_in[0];
    const float* emb  = (const float*)d_in[1];
    const float* W_ih = (const float*)d_in[2];
    const float* W_hh = (const float*)d_in[3];
    const float* b_ih = (const float*)d_in[4];
    const float* b_hh = (const float*)d_in[5];
    const float* W_fc = (const float*)d_in[6];
    const float* b_fc = (const float*)d_in[7];
    float* out = (float*)d_out;

    const int SMEM = (32768 + 8192) * (int)sizeof(float);   // 160 KB
    cudaFuncSetAttribute(kmain, cudaFuncAttributeMaxDynamicSharedMemorySize, SMEM);

    kmain<<<GRID, NT, SMEM>>>(x, emb, W_ih, W_hh, b_ih, b_hh, W_fc, b_fc, out);
}

// round 14
// speedup vs baseline: 1.5762x; 1.5762x over previous
#include <cuda_runtime.h>
#include <math.h>

// Problem constants
#define Vv 32000
#define Ee 512
#define Hh 512
#define G4 2048   // 4*H
#define Bb 64
#define Tt 256
#define GRID 128  // persistent CTAs, 1/SM -> all co-resident
#define NT 256

typedef unsigned long long ull;

// ---------------- device scratch ----------------
__device__ float g_WT_fc[(size_t)Ee * Vv];   // [k][v] transposed W_fc
__device__ float g_h[2][2][Hh * Bb];         // [ping][layer][unit*64+b]
__device__ ull   g_amax[Bb];                 // packed (orderable float | ~idx)
__device__ unsigned g_bar_count;
__device__ volatile unsigned g_bar_gen;

// ---------------- packed f32x2 FMA helpers ----------------
__device__ __forceinline__ void ffma2(ull& d, ull a, ull b) {
    asm("fma.rn.f32x2 %0, %1, %2, %0;" : "+l"(d) : "l"(a), "l"(b));
}
__device__ __forceinline__ ull pack2(float v) {
    ull r; asm("mov.b64 %0, {%1, %1};" : "=l"(r) : "f"(v)); return r;
}
__device__ __forceinline__ float2 unpack2(ull a) {
    float2 r; asm("mov.b64 {%0, %1}, %2;" : "=f"(r.x), "=f"(r.y) : "l"(a)); return r;
}
__device__ __forceinline__ ull amax_pack(float f, int idx) {
    unsigned b = __float_as_uint(f);
    unsigned key = (b & 0x80000000u) ? ~b : (b | 0x80000000u);
    return ((ull)key << 32) | (ull)(0xFFFFFFFFu - (unsigned)idx);
}

// ---------------- grid-wide barrier ----------------
__device__ __forceinline__ void gsync() {
    __threadfence();
    __syncthreads();
    if (threadIdx.x == 0) {
        unsigned gen = g_bar_gen;
        unsigned t = atomicAdd(&g_bar_count, 1u);
        if (t == GRID - 1) {
            g_bar_count = 0;
            __threadfence();
            g_bar_gen = gen + 1;
        } else {
            while (g_bar_gen == gen) { }
        }
    }
    __syncthreads();
}

// smem map (floats): [0, 32768) gate weights; [32768, 40960) stage/scratch (32 KB)
#define STG_OFF 32768

// ---------------- LSTM layer ----------------
// warp w = (m = w>>2: 0 ih / 1 hh, ks = w&3: k-quarter within each 32-k chunk)
// lane: jg = lane>>4 (unit pair), bq = lane&15 (4 batches)
// Acts staged in 32-k double-buffered smem chunks (each element read once/CTA).
// If inp == nullptr, layer input is gathered from emb rows via s_tok (layer 0).
__device__ __forceinline__ void lstm_layer(
    float* wsm, int layer,
    const float* __restrict__ inp,
    const float* __restrict__ emb, const int* __restrict__ s_tok,
    const float* __restrict__ hin, float* __restrict__ hout, float& creg,
    const float* __restrict__ bih, const float* __restrict__ bhh,
    int cta, int tid)
{
    float* stg = wsm + STG_OFF;          // 2 bufs x (2 matrices x 2048 floats)
    int w = tid >> 5, lane = tid & 31;
    int m = w >> 2, ks = w & 3;
    int jg = lane >> 4, bq = lane & 15;
    int gb = tid >> 2, kq = tid & 3;     // gather roles (m0, layer0)

    ull acc[16];
    #pragma unroll
    for (int i = 0; i < 16; i++) acc[i] = 0ull;

    const float4* h4 = (const float4*)hin;
    const float4* i4 = (const float4*)inp;

    // stage chunk 0
    {
        float4 p0 = __ldcg(h4 + tid * 2), p1 = __ldcg(h4 + tid * 2 + 1);
        *(float4*)&stg[2048 + tid * 8]     = p0;
        *(float4*)&stg[2048 + tid * 8 + 4] = p1;
        if (inp) {
            float4 q0 = __ldcg(i4 + tid * 2), q1 = __ldcg(i4 + tid * 2 + 1);
            *(float4*)&stg[tid * 8]     = q0;
            *(float4*)&stg[tid * 8 + 4] = q1;
        } else {
            const float* er = emb + (size_t)s_tok[gb] * Ee + kq * 8;
            float4 q0 = __ldcg((const float4*)er), q1 = __ldcg((const float4*)er + 1);
            stg[(kq * 8 + 0) * 64 + gb] = q0.x; stg[(kq * 8 + 1) * 64 + gb] = q0.y;
            stg[(kq * 8 + 2) * 64 + gb] = q0.z; stg[(kq * 8 + 3) * 64 + gb] = q0.w;
            stg[(kq * 8 + 4) * 64 + gb] = q1.x; stg[(kq * 8 + 5) * 64 + gb] = q1.y;
            stg[(kq * 8 + 6) * 64 + gb] = q1.z; stg[(kq * 8 + 7) * 64 + gb] = q1.w;
        }
    }
    __syncthreads();

    const float* w0p = wsm + (unsigned)(layer * 8 + m * 4 + jg * 2) * 2048;
    const float* w1p = w0p + 2048;

    int d = 0;
    #pragma unroll 1
    for (int c = 0; c < 16; c++) {
        // prefetch chunk c+1
        float4 p0, p1, q0, q1;
        if (c < 15) {
            p0 = __ldcg(h4 + (c + 1) * 512 + tid * 2);
            p1 = __ldcg(h4 + (c + 1) * 512 + tid * 2 + 1);
            if (inp) {
                q0 = __ldcg(i4 + (c + 1) * 512 + tid * 2);
                q1 = __ldcg(i4 + (c + 1) * 512 + tid * 2 + 1);
            } else {
                const float* er = emb + (size_t)s_tok[gb] * Ee + (c + 1) * 32 + kq * 8;
                q0 = __ldcg((const float4*)er);
                q1 = __ldcg((const float4*)er + 1);
            }
        }
        // compute chunk c: this warp handles k_in = ks*8 .. ks*8+7
        const float* ab = stg + d * 4096 + m * 2048 + bq * 4;
        #pragma unroll
        for (int i = 0; i < 8; i++) {
            int kin = ks * 8 + i;
            int kg4 = (c * 32 + kin) * 4;
            float4 w0 = *(const float4*)(w0p + kg4);
            float4 w1 = *(const float4*)(w1p + kg4);
            ulonglong2 av = *(const ulonglong2*)(ab + kin * 64);
            ffma2(acc[0],  av.x, pack2(w0.x)); ffma2(acc[1],  av.y, pack2(w0.x));
            ffma2(acc[2],  av.x, pack2(w0.y)); ffma2(acc[3],  av.y, pack2(w0.y));
            ffma2(acc[4],  av.x, pack2(w0.z)); ffma2(acc[5],  av.y, pack2(w0.z));
            ffma2(acc[6],  av.x, pack2(w0.w)); ffma2(acc[7],  av.y, pack2(w0.w));
            ffma2(acc[8],  av.x, pack2(w1.x)); ffma2(acc[9],  av.y, pack2(w1.x));
            ffma2(acc[10], av.x, pack2(w1.y)); ffma2(acc[11], av.y, pack2(w1.y));
            ffma2(acc[12], av.x, pack2(w1.z)); ffma2(acc[13], av.y, pack2(w1.z));
            ffma2(acc[14], av.x, pack2(w1.w)); ffma2(acc[15], av.y, pack2(w1.w));
        }
        if (c < 15) {
            float* nb = stg + (d ^ 1) * 4096;
            *(float4*)&nb[2048 + tid * 8]     = p0;
            *(float4*)&nb[2048 + tid * 8 + 4] = p1;
            if (inp) {
                *(float4*)&nb[tid * 8]     = q0;
                *(float4*)&nb[tid * 8 + 4] = q1;
            } else {
                nb[(kq * 8 + 0) * 64 + gb] = q0.x; nb[(kq * 8 + 1) * 64 + gb] = q0.y;
                nb[(kq * 8 + 2) * 64 + gb] = q0.z; nb[(kq * 8 + 3) * 64 + gb] = q0.w;
                nb[(kq * 8 + 4) * 64 + gb] = q1.x; nb[(kq * 8 + 5) * 64 + gb] = q1.y;
                nb[(kq * 8 + 6) * 64 + gb] = q1.z; nb[(kq * 8 + 7) * 64 + gb] = q1.w;
            }
        }
        __syncthreads();
        d ^= 1;
    }

    // reduction: 8 partials (2m x 4ks) per output
    ull* sred = (ull*)(wsm + STG_OFF);   // 4096 ull = 32 KB
    #pragma unroll
    for (int i = 0; i < 16; i++) sred[tid * 16 + i] = acc[i];
    __syncthreads();

    {
        int u = tid >> 6, b = tid & 63;
        int jgc = u >> 1, uu = u & 1;
        int bqc = b >> 2, bp = (b >> 1) & 1, be = b & 1;
        int lanec = jgc * 16 + bqc;
        float gate[4];
        #pragma unroll
        for (int g = 0; g < 4; g++) {
            float s = 0.0f;
            #pragma unroll
            for (int ww = 0; ww < 8; ww++) {
                float2 p = unpack2(sred[(ww * 32 + lanec) * 16 + uu * 8 + g * 2 + bp]);
                s += be ? p.y : p.x;
            }
            gate[g] = s;
        }
        int j0 = cta * 4 + u;
        float iv = gate[0] + bih[j0]        + bhh[j0];
        float fv = gate[1] + bih[512 + j0]  + bhh[512 + j0];
        float gv = gate[2] + bih[1024 + j0] + bhh[1024 + j0];
        float ov = gate[3] + bih[1536 + j0] + bhh[1536 + j0];
        float ig = 1.0f / (1.0f + expf(-iv));
        float fg = 1.0f / (1.0f + expf(-fv));
        float og = 1.0f / (1.0f + expf(-ov));
        float cn = fg * creg + ig * tanhf(gv);
        float hn = og * tanhf(cn);
        creg = cn;
        __stcg(&hout[j0 * Bb + b], hn);
    }
    __syncthreads();
}

// ---------------- single persistent kernel ----------------
__global__ void __launch_bounds__(NT, 1)
kmain(const int* __restrict__ x, const float* __restrict__ emb,
      const float* __restrict__ W_ih, const float* __restrict__ W_hh,
      const float* __restrict__ b_ih, const float* __restrict__ b_hh,
      const float* __restrict__ W_fc, const float* __restrict__ bfc,
      float* __restrict__ out)
{
    extern __shared__ float wsm[];
    __shared__ float swv[8][64];
    __shared__ int   swi[8][64];
    __shared__ int   s_tok[64];

    int tid = threadIdx.x;
    int cta = blockIdx.x;

    // ================= per-replay init =================
    ((float2*)&g_h[0][0][0])[cta * 256 + tid] = make_float2(0.0f, 0.0f);
    if (cta == 0 && tid < Bb)
        g_amax[tid] = amax_pack(0.0f, x[tid * Tt]);   // seed step-0 tokens

    // gate weights -> smem: row r = layer*8 + m*4 + u; wsm[r][k] = (wi,wf,wg,wo)
    #pragma unroll 1
    for (int r = 0; r < 16; r++) {
        int l = r >> 3, m = (r >> 2) & 1, u = r & 3;
        const float* base = (m ? W_hh : W_ih) + (size_t)l * G4 * 512
                            + (size_t)(cta * 4 + u) * 512;
        #pragma unroll
        for (int half = 0; half < 2; half++) {
            int k = tid + half * 256;
            float4 wv;
            wv.x = base[k];
            wv.y = base[(size_t)512 * 512 + k];
            wv.z = base[(size_t)1024 * 512 + k];
            wv.w = base[(size_t)1536 * 512 + k];
            *(float4*)&wsm[r * 2048 + k * 4] = wv;
        }
    }
    // transpose W_fc -> g_WT_fc [k][v]: each CTA owns 250 vocab rows
    if (tid < 250) {
        int v = cta * 250 + tid;
        const float4* src = (const float4*)(W_fc + (size_t)v * Ee);
        #pragma unroll 4
        for (int kq = 0; kq < 128; kq++) {
            float4 r = src[kq];
            size_t k = (size_t)kq * 4;
            g_WT_fc[k * Vv + v]       = r.x;
            g_WT_fc[(k + 1) * Vv + v] = r.y;
            g_WT_fc[(k + 2) * Vv + v] = r.z;
            g_WT_fc[(k + 3) * Vv + v] = r.w;
        }
    }

    float creg0 = 0.0f, creg1 = 0.0f;
    gsync();

    // ================= timestep loop =================
    for (int t = 0; t < Tt; t++) {
        int pi = t & 1, po = pi ^ 1;

        // decode this step's tokens (argmax of previous step / seeded x0)
        if (tid < 64) {
            ull pv = __ldcg((const ull*)&g_amax[tid]);
            s_tok[tid] = (int)(0xFFFFFFFFu - (unsigned)(pv & 0xFFFFFFFFull));
        }
        __syncthreads();

        // ---- layer 0 (input gathered from emb rows)
        lstm_layer(wsm, 0, (const float*)0, emb, s_tok,
                   &g_h[pi][0][0], &g_h[po][0][0], creg0,
                   b_ih, b_hh, cta, tid);
        gsync();

        // reset amax for the upcoming FC (everyone has read tokens by now)
        if (cta == 0 && tid < Bb) g_amax[tid] = 0ull;

        // ---- layer 1 (input = fresh layer-0 h)
        lstm_layer(wsm, 1, &g_h[po][0][0], emb, s_tok,
                   &g_h[pi][1][0], &g_h[po][1][0], creg1,
                   b_ih + G4, b_hh + G4, cta, tid);
        gsync();

        // ---- FC head (R11-proven): thread tile 8 vocab x 8 batch ----
        if (cta < 125) {
            int bq = tid >> 5, vg = tid & 31;
            int v0 = cta * 256 + vg * 8;
            const float* hb = &g_h[po][1][0] + bq * 8;

            ull acc[8][4];
            #pragma unroll
            for (int v = 0; v < 8; v++) {
                acc[v][0] = 0; acc[v][1] = 0; acc[v][2] = 0; acc[v][3] = 0;
            }

            float4 wA[2][2], wB[2][2];
            ulonglong2 aA[2][2], aB[2][2];

#define FCLOAD(W, A, kk) { \
    const float4* wr0 = (const float4*)(g_WT_fc + (size_t)(kk) * Vv + v0);       \
    const float4* wr1 = (const float4*)(g_WT_fc + (size_t)((kk) + 1) * Vv + v0); \
    W[0][0] = wr0[0]; W[0][1] = wr0[1];                                          \
    W[1][0] = wr1[0]; W[1][1] = wr1[1];                                          \
    const ulonglong2* ar0 = (const ulonglong2*)(hb + (kk) * Bb);                 \
    const ulonglong2* ar1 = (const ulonglong2*)(hb + ((kk) + 1) * Bb);           \
    A[0][0] = __ldcg(ar0); A[0][1] = __ldcg(ar0 + 1);                            \
    A[1][0] = __ldcg(ar1); A[1][1] = __ldcg(ar1 + 1); }

#define FCCOMP(W, A) {                                                           \
    _Pragma("unroll")                                                            \
    for (int kk = 0; kk < 2; kk++) {                                             \
        ull ap0 = A[kk][0].x, ap1 = A[kk][0].y;                                  \
        ull ap2 = A[kk][1].x, ap3 = A[kk][1].y;                                  \
        const float* wf = (const float*)&W[kk][0];                               \
        _Pragma("unroll")                                                        \
        for (int v = 0; v < 8; v++) {                                            \
            ull wp = pack2(wf[v]);                                               \
            ffma2(acc[v][0], ap0, wp);                                           \
            ffma2(acc[v][1], ap1, wp);                                           \
            ffma2(acc[v][2], ap2, wp);                                           \
            ffma2(acc[v][3], ap3, wp);                                           \
        } } }

            FCLOAD(wA, aA, 0);
            #pragma unroll 1
            for (int k = 0; k < 512; k += 4) {
                int k2 = (k + 2 < 512) ? k + 2 : 0;
                FCLOAD(wB, aB, k2);
                FCCOMP(wA, aA);
                int k4 = (k + 4 < 512) ? k + 4 : 0;
                FCLOAD(wA, aA, k4);
                FCCOMP(wB, aB);
            }
#undef FCLOAD
#undef FCCOMP

            float bias[8];
            {
                float4 b0 = *(const float4*)(bfc + v0);
                float4 b1 = *(const float4*)(bfc + v0 + 4);
                bias[0] = b0.x; bias[1] = b0.y; bias[2] = b0.z; bias[3] = b0.w;
                bias[4] = b1.x; bias[5] = b1.y; bias[6] = b1.z; bias[7] = b1.w;
            }
            #pragma unroll
            for (int bb = 0; bb < 8; bb++) {
                int b = bq * 8 + bb;
                float vals[8];
                #pragma unroll
                for (int v = 0; v < 8; v++) {
                    float2 t2 = unpack2(acc[v][bb >> 1]);
                    vals[v] = ((bb & 1) ? t2.y : t2.x) + bias[v];
                }
                if (t == Tt - 1) {
                    *(float4*)(out + (size_t)b * Vv + v0) =
                        make_float4(vals[0], vals[1], vals[2], vals[3]);
                    *(float4*)(out + (size_t)b * Vv + v0 + 4) =
                        make_float4(vals[4], vals[5], vals[6], vals[7]);
                } else {
                    float mv = vals[0]; int mi = v0;
                    #pragma unroll
                    for (int v = 1; v < 8; v++)
                        if (vals[v] > mv) { mv = vals[v]; mi = v0 + v; }
                    #pragma unroll
                    for (int o = 16; o > 0; o >>= 1) {
                        float ovv = __shfl_down_sync(0xffffffffu, mv, o);
                        int   oii = __shfl_down_sync(0xffffffffu, mi, o);
                        if (ovv > mv || (ovv == mv && oii < mi)) { mv = ovv; mi = oii; }
                    }
                    if (vg == 0) { swv[bq][0] = 0.0f; }  // keep swv live
                    if (vg == 0) atomicMax(&g_amax[b], amax_pack(mv, mi));
                }
            }
        }
        gsync();
    }
}

// ---------------- host driver ----------------
extern "C" void kernel_launch(void* const* d_in, const int* in_sizes, int n_in,
                              void* d_out, int out_size) {
    const int*   x    = (const int*)d_in[0];
    const float* emb  = (const float*)d_in[1];
    const float* W_ih = (const float*)d_in[2];
    const float* W_hh = (const float*)d_in[3];
    const float* b_ih = (const float*)d_in[4];
    const float* b_hh = (const float*)d_in[5];
    const float* W_fc = (const float*)d_in[6];
    const float* b_fc = (const float*)d_in[7];
    float* out = (float*)d_out;

    const int SMEM = (32768 + 8192) * (int)sizeof(float);   // 160 KB
    cudaFuncSetAttribute(kmain, cudaFuncAttributeMaxDynamicSharedMemorySize, SMEM);

    kmain<<<GRID, NT, SMEM>>>(x, emb, W_ih, W_hh, b_ih, b_hh, W_fc, b_fc, out);
}